// round 1
// baseline (speedup 1.0000x reference)
#include <cuda_runtime.h>
#include <math.h>

// Problem constants (fixed by setup_inputs)
#define Bc   2
#define Tc   2048
#define Cc   1024
#define NH   16
#define HD   64
#define Mtot (Bc * Tc)        // 4096
#define N1   (3 * Cc)         // 3072
#define Kc   Cc               // 1024
#define Rr   16
#define LORA_SCALE (1.0f / 16.0f)

// Scratch (device globals: allocation-free rule)
__device__ float g_qkv[Mtot * N1];   // 48 MB
__device__ float g_y[Mtot * Cc];     // 16 MB
__device__ float g_xa[Mtot * Rr];
__device__ float g_ya[Mtot * Rr];

// ---------------------------------------------------------------------------
// LoRA A projection: XA[m,r] = sum_k X[m,k] * A[r,k]   (A: R x K row-major)
// grid = M blocks, 128 threads
// ---------------------------------------------------------------------------
__global__ void lora_a_kernel(const float* __restrict__ X,
                              const float* __restrict__ Aw,
                              float* __restrict__ XA)
{
    const int m   = blockIdx.x;
    const int tid = threadIdx.x;
    float acc[Rr];
#pragma unroll
    for (int r = 0; r < Rr; r++) acc[r] = 0.f;

    const float* xrow = X + (size_t)m * Kc;
    for (int k = tid; k < Kc; k += 128) {
        float xv = xrow[k];
#pragma unroll
        for (int r = 0; r < Rr; r++) acc[r] += xv * Aw[r * Kc + k];
    }
    // warp reduce
#pragma unroll
    for (int r = 0; r < Rr; r++) {
        float v = acc[r];
#pragma unroll
        for (int off = 16; off; off >>= 1) v += __shfl_xor_sync(0xffffffffu, v, off);
        acc[r] = v;
    }
    __shared__ float red[4][Rr];
    const int warp = tid >> 5, lane = tid & 31;
    if (lane == 0) {
#pragma unroll
        for (int r = 0; r < Rr; r++) red[warp][r] = acc[r];
    }
    __syncthreads();
    if (tid < Rr) {
        XA[(size_t)m * Rr + tid] = red[0][tid] + red[1][tid] + red[2][tid] + red[3][tid];
    }
}

// ---------------------------------------------------------------------------
// Fused GEMM + bias + LoRA epilogue:
//   out[m,n] = sum_k A[m,k]*W[n,k] + bias[n] + LORA_SCALE * sum_r XA[m,r]*LB[n,r]
// A: MxK row-major, W: NxK row-major (i.e. out = A @ W^T)
// Tile: 64x64, BK=16, 256 threads, 4x4 micro-tile
// ---------------------------------------------------------------------------
#define BM 64
#define BN 64
#define BK 16

__global__ __launch_bounds__(256)
void gemm_lora_kernel(const float* __restrict__ A,
                      const float* __restrict__ W,
                      const float* __restrict__ bias,
                      const float* __restrict__ XA,
                      const float* __restrict__ LB,
                      float* __restrict__ out,
                      int N)
{
    __shared__ float As[BK][BM];
    __shared__ float Ws[BK][BN];

    const int tid  = threadIdx.x;
    const int row0 = blockIdx.y * BM;
    const int col0 = blockIdx.x * BN;
    const int tx   = tid & 15;   // 0..15  -> 4 cols each
    const int ty   = tid >> 4;   // 0..15  -> 4 rows each

    const int lr = tid >> 2;          // 0..63 row within tile for loading
    const int lk = (tid & 3) * 4;     // k offset (float4)

    float acc[4][4];
#pragma unroll
    for (int i = 0; i < 4; i++)
#pragma unroll
        for (int j = 0; j < 4; j++) acc[i][j] = 0.f;

    for (int k0 = 0; k0 < Kc; k0 += BK) {
        float4 av = *(const float4*)&A[(size_t)(row0 + lr) * Kc + k0 + lk];
        float4 wv = *(const float4*)&W[(size_t)(col0 + lr) * Kc + k0 + lk];
        As[lk + 0][lr] = av.x; As[lk + 1][lr] = av.y;
        As[lk + 2][lr] = av.z; As[lk + 3][lr] = av.w;
        Ws[lk + 0][lr] = wv.x; Ws[lk + 1][lr] = wv.y;
        Ws[lk + 2][lr] = wv.z; Ws[lk + 3][lr] = wv.w;
        __syncthreads();

#pragma unroll
        for (int k = 0; k < BK; k++) {
            float4 a4 = *(const float4*)&As[k][ty * 4];
            float4 b4 = *(const float4*)&Ws[k][tx * 4];
            acc[0][0] += a4.x * b4.x; acc[0][1] += a4.x * b4.y;
            acc[0][2] += a4.x * b4.z; acc[0][3] += a4.x * b4.w;
            acc[1][0] += a4.y * b4.x; acc[1][1] += a4.y * b4.y;
            acc[1][2] += a4.y * b4.z; acc[1][3] += a4.y * b4.w;
            acc[2][0] += a4.z * b4.x; acc[2][1] += a4.z * b4.y;
            acc[2][2] += a4.z * b4.z; acc[2][3] += a4.z * b4.w;
            acc[3][0] += a4.w * b4.x; acc[3][1] += a4.w * b4.y;
            acc[3][2] += a4.w * b4.z; acc[3][3] += a4.w * b4.w;
        }
        __syncthreads();
    }

    // epilogue: bias + LoRA rank-16 correction
#pragma unroll
    for (int i = 0; i < 4; i++) {
        const int m = row0 + ty * 4 + i;
        float xa[Rr];
#pragma unroll
        for (int r = 0; r < Rr; r++) xa[r] = XA[(size_t)m * Rr + r];
#pragma unroll
        for (int j = 0; j < 4; j++) {
            const int n = col0 + tx * 4 + j;
            float dot = 0.f;
#pragma unroll
            for (int r = 0; r < Rr; r++) dot += xa[r] * LB[(size_t)n * Rr + r];
            out[(size_t)m * N + n] = acc[i][j] + bias[n] + dot * LORA_SCALE;
        }
    }
}

// ---------------------------------------------------------------------------
// Flash-attention (fp32, causal). One block = 64 query rows of one (b,h).
// blockDim = 256: tx = tid&3 owns hd slice [tx*16, tx*16+16), ty = tid>>2 owns
// query row ty within the tile. Online softmax; score values broadcast within
// the 4-lane group via shfl (no P smem needed).
// ---------------------------------------------------------------------------
__global__ __launch_bounds__(256)
void attn_kernel(const float* __restrict__ qkv, float* __restrict__ Y)
{
    const int qb = blockIdx.x;          // query tile 0..31
    const int bh = blockIdx.y;          // 0..31
    const int b  = bh >> 4;
    const int h  = bh & 15;

    const int tid = threadIdx.x;
    const int tx  = tid & 3;
    const int ty  = tid >> 2;

    __shared__ float Ks[64][64];
    __shared__ float Vs[64][64];

    const size_t rowbase = (size_t)(b * Tc) * N1;
    const float* qptr = qkv + rowbase + (size_t)h * HD;
    const float* kptr = qptr + Cc;
    const float* vptr = qptr + 2 * Cc;

    const int qg = qb * 64 + ty;

    float qreg[16];
#pragma unroll
    for (int u = 0; u < 4; u++) {
        float4 v = *(const float4*)&qptr[(size_t)qg * N1 + tx * 16 + u * 4];
        qreg[u * 4 + 0] = v.x; qreg[u * 4 + 1] = v.y;
        qreg[u * 4 + 2] = v.z; qreg[u * 4 + 3] = v.w;
    }

    float out[16];
#pragma unroll
    for (int i = 0; i < 16; i++) out[i] = 0.f;
    float m_run = -INFINITY, l_run = 0.f;

    const int lane      = tid & 31;
    const int base_lane = lane & ~3;    // first lane of this 4-lane group

    for (int jt = 0; jt <= qb; jt++) {
        // load K and V tiles (64x64 each)
#pragma unroll
        for (int u = 0; u < 4; u++) {
            int idx = tid + u * 256;          // float4 index 0..1023
            int kk  = idx >> 4;               // row
            int dd  = (idx & 15) * 4;         // col
            size_t goff = (size_t)(jt * 64 + kk) * N1 + dd;
            *(float4*)&Ks[kk][dd] = *(const float4*)&kptr[goff];
            *(float4*)&Vs[kk][dd] = *(const float4*)&vptr[goff];
        }
        __syncthreads();

        // scores: each group-of-4 computes all 64 dot products; thread tx
        // keeps s[j] for j % 4 == tx.
        float s[16];
#pragma unroll
        for (int j = 0; j < 64; j++) {
            const float* kr = &Ks[j][tx * 16];
            float p = 0.f;
#pragma unroll
            for (int i = 0; i < 16; i++) p += qreg[i] * kr[i];
            p += __shfl_xor_sync(0xffffffffu, p, 1);
            p += __shfl_xor_sync(0xffffffffu, p, 2);
            if ((j & 3) == tx) {
                int kg = jt * 64 + j;
                float sv = p * 0.125f;               // 1/sqrt(64)
                if (kg > qg) sv = -INFINITY;
                s[j >> 2] = sv;
            }
        }

        // online softmax
        float tmax = -INFINITY;
#pragma unroll
        for (int jj = 0; jj < 16; jj++) tmax = fmaxf(tmax, s[jj]);
        tmax = fmaxf(tmax, __shfl_xor_sync(0xffffffffu, tmax, 1));
        tmax = fmaxf(tmax, __shfl_xor_sync(0xffffffffu, tmax, 2));

        const float m_new = fmaxf(m_run, tmax);
        const float corr  = __expf(m_run - m_new);
        float lsum = 0.f;
#pragma unroll
        for (int jj = 0; jj < 16; jj++) {
            float pv = __expf(s[jj] - m_new);
            s[jj] = pv;
            lsum += pv;
        }
        lsum += __shfl_xor_sync(0xffffffffu, lsum, 1);
        lsum += __shfl_xor_sync(0xffffffffu, lsum, 2);
        l_run = l_run * corr + lsum;
        m_run = m_new;
#pragma unroll
        for (int i = 0; i < 16; i++) out[i] *= corr;

        // PV: p_j broadcast from owner lane within the group
#pragma unroll
        for (int j = 0; j < 64; j++) {
            float pv = __shfl_sync(0xffffffffu, s[j >> 2], base_lane + (j & 3));
            const float* vr = &Vs[j][tx * 16];
#pragma unroll
            for (int i = 0; i < 16; i++) out[i] += pv * vr[i];
        }
        __syncthreads();
    }

    const float inv = 1.f / l_run;
    float* yp = Y + ((size_t)(b * Tc + qg)) * Cc + h * HD + tx * 16;
#pragma unroll
    for (int u = 0; u < 4; u++) {
        float4 v;
        v.x = out[u * 4 + 0] * inv; v.y = out[u * 4 + 1] * inv;
        v.z = out[u * 4 + 2] * inv; v.w = out[u * 4 + 3] * inv;
        *(float4*)&yp[u * 4] = v;
    }
}

// ---------------------------------------------------------------------------
// Launcher
// ---------------------------------------------------------------------------
extern "C" void kernel_launch(void* const* d_in, const int* in_sizes, int n_in,
                              void* d_out, int out_size)
{
    const float* x        = (const float*)d_in[0];
    const float* w_attn   = (const float*)d_in[1];
    const float* b_attn   = (const float*)d_in[2];
    const float* la_attn  = (const float*)d_in[3];
    const float* lb_attn  = (const float*)d_in[4];
    const float* w_proj   = (const float*)d_in[5];
    const float* b_proj   = (const float*)d_in[6];
    const float* la_proj  = (const float*)d_in[7];
    const float* lb_proj  = (const float*)d_in[8];
    float* out            = (float*)d_out;

    float *qkv, *y, *xa, *ya;
    cudaGetSymbolAddress((void**)&qkv, g_qkv);
    cudaGetSymbolAddress((void**)&y,   g_y);
    cudaGetSymbolAddress((void**)&xa,  g_xa);
    cudaGetSymbolAddress((void**)&ya,  g_ya);

    // 1. xa = x @ A_attn^T
    lora_a_kernel<<<Mtot, 128>>>(x, la_attn, xa);

    // 2. qkv = x @ W_attn^T + b + xa @ B_attn^T * scale
    {
        dim3 grid(N1 / BN, Mtot / BM);
        gemm_lora_kernel<<<grid, 256>>>(x, w_attn, b_attn, xa, lb_attn, qkv, N1);
    }

    // 3. attention
    {
        dim3 grid(Tc / 64, Bc * NH);
        attn_kernel<<<grid, 256>>>(qkv, y);
    }

    // 4. ya = y @ A_proj^T
    lora_a_kernel<<<Mtot, 128>>>(y, la_proj, ya);

    // 5. out = y @ W_proj^T + b + ya @ B_proj^T * scale
    {
        dim3 grid(Cc / BN, Mtot / BM);
        gemm_lora_kernel<<<grid, 256>>>(y, w_proj, b_proj, ya, lb_proj, out, Cc);
    }
}

// round 2
// speedup vs baseline: 5.8370x; 5.8370x over previous
#include <cuda_runtime.h>
#include <math.h>

// Problem constants (fixed by setup_inputs)
#define Bc   2
#define Tc   2048
#define Cc   1024
#define NH   16
#define HD   64
#define Mtot (Bc * Tc)        // 4096
#define N1   (3 * Cc)         // 3072
#define Kc   Cc               // 1024
#define Rr   16
#define LORA_SCALE (1.0f / 16.0f)

// Scratch (device globals: allocation-free rule)
__device__ float g_qkv[Mtot * N1];   // 48 MB
__device__ float g_y[Mtot * Cc];     // 16 MB
__device__ float g_xa[Mtot * Rr];
__device__ float g_ya[Mtot * Rr];

// ---------------------------------------------------------------------------
// helpers
// ---------------------------------------------------------------------------
__device__ __forceinline__ unsigned f2t(float f) {
    unsigned u;
    asm("cvt.rna.tf32.f32 %0, %1;" : "=r"(u) : "f"(f));
    return u;
}
__device__ __forceinline__ float f2tf(float f) { return __uint_as_float(f2t(f)); }

__device__ __forceinline__ void mma_tf32(float* d, const unsigned* a,
                                         unsigned b0, unsigned b1) {
    asm volatile(
        "mma.sync.aligned.m16n8k8.row.col.f32.tf32.tf32.f32 "
        "{%0,%1,%2,%3},{%4,%5,%6,%7},{%8,%9},{%0,%1,%2,%3};\n"
        : "+f"(d[0]), "+f"(d[1]), "+f"(d[2]), "+f"(d[3])
        : "r"(a[0]), "r"(a[1]), "r"(a[2]), "r"(a[3]), "r"(b0), "r"(b1));
}

// ---------------------------------------------------------------------------
// LoRA A projection: XA[m,r] = sum_k X[m,k] * A[r,k]
// warp per row, float4 loads. grid = Mtot/8 blocks, 256 threads.
// ---------------------------------------------------------------------------
__global__ __launch_bounds__(256)
void lora_a_kernel(const float* __restrict__ X,
                   const float* __restrict__ Aw,
                   float* __restrict__ XA)
{
    const int lane = threadIdx.x & 31;
    const int w    = threadIdx.x >> 5;
    const int m    = blockIdx.x * 8 + w;

    float acc[Rr];
#pragma unroll
    for (int r = 0; r < Rr; r++) acc[r] = 0.f;

    const float* xr = X + (size_t)m * Kc;
#pragma unroll
    for (int it = 0; it < 8; it++) {
        int k = (it * 32 + lane) * 4;
        float4 xv = *(const float4*)&xr[k];
#pragma unroll
        for (int r = 0; r < Rr; r++) {
            float4 av = *(const float4*)&Aw[r * Kc + k];
            acc[r] += xv.x * av.x + xv.y * av.y + xv.z * av.z + xv.w * av.w;
        }
    }
#pragma unroll
    for (int r = 0; r < Rr; r++) {
        float v = acc[r];
#pragma unroll
        for (int off = 16; off; off >>= 1) v += __shfl_xor_sync(0xffffffffu, v, off);
        acc[r] = v;
    }
    if (lane == 0) {
        float4* dst = (float4*)&XA[(size_t)m * Rr];
        dst[0] = make_float4(acc[0],  acc[1],  acc[2],  acc[3]);
        dst[1] = make_float4(acc[4],  acc[5],  acc[6],  acc[7]);
        dst[2] = make_float4(acc[8],  acc[9],  acc[10], acc[11]);
        dst[3] = make_float4(acc[12], acc[13], acc[14], acc[15]);
    }
}

// ---------------------------------------------------------------------------
// Fused GEMM (tf32 tensor cores) + bias, LoRA folded into K loop:
//   out = [A | XA] @ [W | LB*scale]^T + bias
// A: MxK row-major, W: NxK row-major, XA: Mx16, LB: Nx16.
// Tile 128x128, BK=16 (65 K-stages incl. LoRA), 256 threads = 8 warps (2x4),
// warp tile 64x32 (4x4 grid of m16n8 mma).
// ---------------------------------------------------------------------------
#define GBM 128
#define GBN 128
#define GBK 16
#define GPAD 20

__global__ __launch_bounds__(256, 2)
void gemm_lora_tc(const float* __restrict__ A, const float* __restrict__ W,
                  const float* __restrict__ bias, const float* __restrict__ XA,
                  const float* __restrict__ LB, float* __restrict__ out, int N)
{
    __shared__ float As[2][GBM][GPAD];
    __shared__ float Ws[2][GBN][GPAD];

    const int tid  = threadIdx.x;
    const int row0 = blockIdx.y * GBM;
    const int col0 = blockIdx.x * GBN;
    const int lane = tid & 31, wid = tid >> 5;
    const int wm = (wid >> 2) * 64;
    const int wn = (wid & 3) * 32;
    const int g  = lane >> 2, tq = lane & 3;

    const int lrow = tid >> 1;
    const int lk   = (tid & 1) * 8;

    float acc[4][4][4];
#pragma unroll
    for (int mt = 0; mt < 4; mt++)
#pragma unroll
        for (int nt = 0; nt < 4; nt++)
#pragma unroll
            for (int i = 0; i < 4; i++) acc[mt][nt][i] = 0.f;

    const int NST = Kc / GBK + 1;   // 65: last stage is the LoRA rank-16 block

    // stage 0 load
    {
        const float* pa = A + (size_t)(row0 + lrow) * Kc + lk;
        const float* pw = W + (size_t)(col0 + lrow) * Kc + lk;
        float4 a0 = *(const float4*)pa,       a1 = *(const float4*)(pa + 4);
        float4 w0 = *(const float4*)pw,       w1 = *(const float4*)(pw + 4);
        As[0][lrow][lk + 0] = f2tf(a0.x); As[0][lrow][lk + 1] = f2tf(a0.y);
        As[0][lrow][lk + 2] = f2tf(a0.z); As[0][lrow][lk + 3] = f2tf(a0.w);
        As[0][lrow][lk + 4] = f2tf(a1.x); As[0][lrow][lk + 5] = f2tf(a1.y);
        As[0][lrow][lk + 6] = f2tf(a1.z); As[0][lrow][lk + 7] = f2tf(a1.w);
        Ws[0][lrow][lk + 0] = f2tf(w0.x); Ws[0][lrow][lk + 1] = f2tf(w0.y);
        Ws[0][lrow][lk + 2] = f2tf(w0.z); Ws[0][lrow][lk + 3] = f2tf(w0.w);
        Ws[0][lrow][lk + 4] = f2tf(w1.x); Ws[0][lrow][lk + 5] = f2tf(w1.y);
        Ws[0][lrow][lk + 6] = f2tf(w1.z); Ws[0][lrow][lk + 7] = f2tf(w1.w);
    }
    __syncthreads();

    for (int s = 0; s < NST; s++) {
        const int cur = s & 1;
        float4 a0, a1, w0, w1;
        const bool has_next = (s + 1 < NST);
        if (has_next) {
            if (s + 1 == NST - 1) {   // LoRA stage
                const float* pa = XA + (size_t)(row0 + lrow) * Rr + lk;
                const float* pw = LB + (size_t)(col0 + lrow) * Rr + lk;
                a0 = *(const float4*)pa; a1 = *(const float4*)(pa + 4);
                w0 = *(const float4*)pw; w1 = *(const float4*)(pw + 4);
                w0.x *= LORA_SCALE; w0.y *= LORA_SCALE; w0.z *= LORA_SCALE; w0.w *= LORA_SCALE;
                w1.x *= LORA_SCALE; w1.y *= LORA_SCALE; w1.z *= LORA_SCALE; w1.w *= LORA_SCALE;
            } else {
                const float* pa = A + (size_t)(row0 + lrow) * Kc + (s + 1) * GBK + lk;
                const float* pw = W + (size_t)(col0 + lrow) * Kc + (s + 1) * GBK + lk;
                a0 = *(const float4*)pa; a1 = *(const float4*)(pa + 4);
                w0 = *(const float4*)pw; w1 = *(const float4*)(pw + 4);
            }
        }

#pragma unroll
        for (int ks = 0; ks < 2; ks++) {
            const int k = ks * 8;
            unsigned af[4][4], bf[4][2];
#pragma unroll
            for (int mt = 0; mt < 4; mt++) {
                const int r0 = wm + mt * 16;
                af[mt][0] = __float_as_uint(As[cur][r0 + g][k + tq]);
                af[mt][1] = __float_as_uint(As[cur][r0 + g + 8][k + tq]);
                af[mt][2] = __float_as_uint(As[cur][r0 + g][k + tq + 4]);
                af[mt][3] = __float_as_uint(As[cur][r0 + g + 8][k + tq + 4]);
            }
#pragma unroll
            for (int nt = 0; nt < 4; nt++) {
                const int c0 = wn + nt * 8;
                bf[nt][0] = __float_as_uint(Ws[cur][c0 + g][k + tq]);
                bf[nt][1] = __float_as_uint(Ws[cur][c0 + g][k + tq + 4]);
            }
#pragma unroll
            for (int mt = 0; mt < 4; mt++)
#pragma unroll
                for (int nt = 0; nt < 4; nt++)
                    mma_tf32(acc[mt][nt], af[mt], bf[nt][0], bf[nt][1]);
        }

        if (has_next) {
            const int nxt = cur ^ 1;
            As[nxt][lrow][lk + 0] = f2tf(a0.x); As[nxt][lrow][lk + 1] = f2tf(a0.y);
            As[nxt][lrow][lk + 2] = f2tf(a0.z); As[nxt][lrow][lk + 3] = f2tf(a0.w);
            As[nxt][lrow][lk + 4] = f2tf(a1.x); As[nxt][lrow][lk + 5] = f2tf(a1.y);
            As[nxt][lrow][lk + 6] = f2tf(a1.z); As[nxt][lrow][lk + 7] = f2tf(a1.w);
            Ws[nxt][lrow][lk + 0] = f2tf(w0.x); Ws[nxt][lrow][lk + 1] = f2tf(w0.y);
            Ws[nxt][lrow][lk + 2] = f2tf(w0.z); Ws[nxt][lrow][lk + 3] = f2tf(w0.w);
            Ws[nxt][lrow][lk + 4] = f2tf(w1.x); Ws[nxt][lrow][lk + 5] = f2tf(w1.y);
            Ws[nxt][lrow][lk + 6] = f2tf(w1.z); Ws[nxt][lrow][lk + 7] = f2tf(w1.w);
            __syncthreads();
        }
    }

    // epilogue: add bias, write fp32
#pragma unroll
    for (int nt = 0; nt < 4; nt++) {
        const int c = col0 + wn + nt * 8 + 2 * tq;
        const float b0 = bias[c], b1 = bias[c + 1];
#pragma unroll
        for (int mt = 0; mt < 4; mt++) {
            const int r = row0 + wm + mt * 16 + g;
            float2 lo; lo.x = acc[mt][nt][0] + b0; lo.y = acc[mt][nt][1] + b1;
            *(float2*)&out[(size_t)r * N + c] = lo;
            float2 hi; hi.x = acc[mt][nt][2] + b0; hi.y = acc[mt][nt][3] + b1;
            *(float2*)&out[(size_t)(r + 8) * N + c] = hi;
        }
    }
}

// ---------------------------------------------------------------------------
// Flash attention with tf32 tensor cores.
// Block = 64 query rows of one (b,h); 128 threads = 4 warps, warp owns 16 rows.
// Smem (dynamic): Ks[64][68], Vs[64][72], Ps[64][68] — strides chosen so that
// all mma fragment read patterns are bank-conflict-free.
// ---------------------------------------------------------------------------
#define KS_STRIDE 68
#define VS_STRIDE 72
#define PS_STRIDE 68
#define ATTN_SMEM ((64 * KS_STRIDE + 64 * VS_STRIDE + 64 * PS_STRIDE) * 4)

__global__ void attn_tc(const float* __restrict__ qkv, float* __restrict__ Y)
{
    extern __shared__ float sm[];
    float (*Ks)[KS_STRIDE] = (float(*)[KS_STRIDE])sm;
    float (*Vs)[VS_STRIDE] = (float(*)[VS_STRIDE])(sm + 64 * KS_STRIDE);
    float (*Ps)[PS_STRIDE] = (float(*)[PS_STRIDE])(sm + 64 * KS_STRIDE + 64 * VS_STRIDE);

    const int qb  = blockIdx.x;
    const int bh  = blockIdx.y;
    const int b   = bh >> 4;
    const int h   = bh & 15;
    const int tid = threadIdx.x;
    const int lane = tid & 31, wid = tid >> 5;
    const int wm  = wid * 16;
    const int g   = lane >> 2, tq = lane & 3;
    const int qg0 = qb * 64;

    const float* qptr = qkv + (size_t)(b * Tc) * N1 + h * HD;
    const float* kptr = qptr + Cc;
    const float* vptr = qptr + 2 * Cc;

    // stage Q tile into Ps, then extract scaled tf32 A-fragments
#pragma unroll
    for (int u = 0; u < 8; u++) {
        int idx = tid + u * 128;
        int r = idx >> 4, c4 = (idx & 15) * 4;
        *(float4*)&Ps[r][c4] = *(const float4*)&qptr[(size_t)(qg0 + r) * N1 + c4];
    }
    __syncthreads();

    unsigned qa[8][4];
#pragma unroll
    for (int kb = 0; kb < 8; kb++) {
        qa[kb][0] = f2t(Ps[wm + g][kb * 8 + tq] * 0.125f);
        qa[kb][1] = f2t(Ps[wm + g + 8][kb * 8 + tq] * 0.125f);
        qa[kb][2] = f2t(Ps[wm + g][kb * 8 + tq + 4] * 0.125f);
        qa[kb][3] = f2t(Ps[wm + g + 8][kb * 8 + tq + 4] * 0.125f);
    }

    float o[8][4];
#pragma unroll
    for (int nt = 0; nt < 8; nt++)
#pragma unroll
        for (int i = 0; i < 4; i++) o[nt][i] = 0.f;
    float m_lo = -INFINITY, m_hi = -INFINITY, l_lo = 0.f, l_hi = 0.f;

    const int r_lo = qg0 + wm + g;
    const int r_hi = r_lo + 8;

    for (int jt = 0; jt <= qb; jt++) {
        __syncthreads();   // previous tile's smem reads complete
#pragma unroll
        for (int u = 0; u < 8; u++) {
            int idx = tid + u * 128;
            int r = idx >> 4, c4 = (idx & 15) * 4;
            size_t go = (size_t)(jt * 64 + r) * N1 + c4;
            float4 kv = *(const float4*)&kptr[go];
            Ks[r][c4 + 0] = f2tf(kv.x); Ks[r][c4 + 1] = f2tf(kv.y);
            Ks[r][c4 + 2] = f2tf(kv.z); Ks[r][c4 + 3] = f2tf(kv.w);
            float4 vv = *(const float4*)&vptr[go];
            Vs[r][c4 + 0] = f2tf(vv.x); Vs[r][c4 + 1] = f2tf(vv.y);
            Vs[r][c4 + 2] = f2tf(vv.z); Vs[r][c4 + 3] = f2tf(vv.w);
        }
        __syncthreads();

        // S = Q @ K^T (scaled)
        float sc[8][4];
#pragma unroll
        for (int nt = 0; nt < 8; nt++) {
#pragma unroll
            for (int i = 0; i < 4; i++) sc[nt][i] = 0.f;
#pragma unroll
            for (int kb = 0; kb < 8; kb++) {
                unsigned b0 = __float_as_uint(Ks[nt * 8 + g][kb * 8 + tq]);
                unsigned b1 = __float_as_uint(Ks[nt * 8 + g][kb * 8 + tq + 4]);
                mma_tf32(sc[nt], qa[kb], b0, b1);
            }
        }

        // causal mask on the diagonal tile
        if (jt == qb) {
#pragma unroll
            for (int nt = 0; nt < 8; nt++) {
                const int c = qg0 + nt * 8 + 2 * tq;
                if (c     > r_lo) sc[nt][0] = -INFINITY;
                if (c + 1 > r_lo) sc[nt][1] = -INFINITY;
                if (c     > r_hi) sc[nt][2] = -INFINITY;
                if (c + 1 > r_hi) sc[nt][3] = -INFINITY;
            }
        }

        // online softmax (rows split lo/hi)
        float tmax_lo = -INFINITY, tmax_hi = -INFINITY;
#pragma unroll
        for (int nt = 0; nt < 8; nt++) {
            tmax_lo = fmaxf(tmax_lo, fmaxf(sc[nt][0], sc[nt][1]));
            tmax_hi = fmaxf(tmax_hi, fmaxf(sc[nt][2], sc[nt][3]));
        }
        tmax_lo = fmaxf(tmax_lo, __shfl_xor_sync(0xffffffffu, tmax_lo, 1));
        tmax_lo = fmaxf(tmax_lo, __shfl_xor_sync(0xffffffffu, tmax_lo, 2));
        tmax_hi = fmaxf(tmax_hi, __shfl_xor_sync(0xffffffffu, tmax_hi, 1));
        tmax_hi = fmaxf(tmax_hi, __shfl_xor_sync(0xffffffffu, tmax_hi, 2));

        const float mn_lo = fmaxf(m_lo, tmax_lo);
        const float mn_hi = fmaxf(m_hi, tmax_hi);
        const float corr_lo = __expf(m_lo - mn_lo);
        const float corr_hi = __expf(m_hi - mn_hi);
        m_lo = mn_lo; m_hi = mn_hi;

        float ls_lo = 0.f, ls_hi = 0.f;
#pragma unroll
        for (int nt = 0; nt < 8; nt++) {
            float p0 = __expf(sc[nt][0] - mn_lo);
            float p1 = __expf(sc[nt][1] - mn_lo);
            float p2 = __expf(sc[nt][2] - mn_hi);
            float p3 = __expf(sc[nt][3] - mn_hi);
            ls_lo += p0 + p1;
            ls_hi += p2 + p3;
            float2 v0; v0.x = f2tf(p0); v0.y = f2tf(p1);
            *(float2*)&Ps[wm + g][nt * 8 + 2 * tq] = v0;
            float2 v1; v1.x = f2tf(p2); v1.y = f2tf(p3);
            *(float2*)&Ps[wm + g + 8][nt * 8 + 2 * tq] = v1;
        }
        ls_lo += __shfl_xor_sync(0xffffffffu, ls_lo, 1);
        ls_lo += __shfl_xor_sync(0xffffffffu, ls_lo, 2);
        ls_hi += __shfl_xor_sync(0xffffffffu, ls_hi, 1);
        ls_hi += __shfl_xor_sync(0xffffffffu, ls_hi, 2);
        l_lo = l_lo * corr_lo + ls_lo;
        l_hi = l_hi * corr_hi + ls_hi;

#pragma unroll
        for (int nt = 0; nt < 8; nt++) {
            o[nt][0] *= corr_lo; o[nt][1] *= corr_lo;
            o[nt][2] *= corr_hi; o[nt][3] *= corr_hi;
        }
        __syncwarp();

        // O += P @ V
#pragma unroll
        for (int kb = 0; kb < 8; kb++) {
            unsigned pa[4];
            pa[0] = __float_as_uint(Ps[wm + g][kb * 8 + tq]);
            pa[1] = __float_as_uint(Ps[wm + g + 8][kb * 8 + tq]);
            pa[2] = __float_as_uint(Ps[wm + g][kb * 8 + tq + 4]);
            pa[3] = __float_as_uint(Ps[wm + g + 8][kb * 8 + tq + 4]);
#pragma unroll
            for (int nt = 0; nt < 8; nt++) {
                unsigned b0 = __float_as_uint(Vs[kb * 8 + tq][nt * 8 + g]);
                unsigned b1 = __float_as_uint(Vs[kb * 8 + tq + 4][nt * 8 + g]);
                mma_tf32(o[nt], pa, b0, b1);
            }
        }
    }

    const float inv_lo = 1.f / l_lo;
    const float inv_hi = 1.f / l_hi;
#pragma unroll
    for (int nt = 0; nt < 8; nt++) {
        const int c = h * HD + nt * 8 + 2 * tq;
        float2 v; v.x = o[nt][0] * inv_lo; v.y = o[nt][1] * inv_lo;
        *(float2*)&Y[(size_t)(b * Tc + r_lo) * Cc + c] = v;
        float2 v2; v2.x = o[nt][2] * inv_hi; v2.y = o[nt][3] * inv_hi;
        *(float2*)&Y[(size_t)(b * Tc + r_hi) * Cc + c] = v2;
    }
}

// ---------------------------------------------------------------------------
// Launcher
// ---------------------------------------------------------------------------
extern "C" void kernel_launch(void* const* d_in, const int* in_sizes, int n_in,
                              void* d_out, int out_size)
{
    const float* x        = (const float*)d_in[0];
    const float* w_attn   = (const float*)d_in[1];
    const float* b_attn   = (const float*)d_in[2];
    const float* la_attn  = (const float*)d_in[3];
    const float* lb_attn  = (const float*)d_in[4];
    const float* w_proj   = (const float*)d_in[5];
    const float* b_proj   = (const float*)d_in[6];
    const float* la_proj  = (const float*)d_in[7];
    const float* lb_proj  = (const float*)d_in[8];
    float* out            = (float*)d_out;

    float *qkv, *y, *xa, *ya;
    cudaGetSymbolAddress((void**)&qkv, g_qkv);
    cudaGetSymbolAddress((void**)&y,   g_y);
    cudaGetSymbolAddress((void**)&xa,  g_xa);
    cudaGetSymbolAddress((void**)&ya,  g_ya);

    cudaFuncSetAttribute(attn_tc, cudaFuncAttributeMaxDynamicSharedMemorySize,
                         ATTN_SMEM);

    // 1. xa = x @ A_attn^T
    lora_a_kernel<<<Mtot / 8, 256>>>(x, la_attn, xa);

    // 2. qkv = [x|xa] @ [W_attn|LB*s]^T + b
    {
        dim3 grid(N1 / GBN, Mtot / GBM);
        gemm_lora_tc<<<grid, 256>>>(x, w_attn, b_attn, xa, lb_attn, qkv, N1);
    }

    // 3. attention
    {
        dim3 grid(Tc / 64, Bc * NH);
        attn_tc<<<grid, 128, ATTN_SMEM>>>(qkv, y);
    }

    // 4. ya = y @ A_proj^T
    lora_a_kernel<<<Mtot / 8, 256>>>(y, la_proj, ya);

    // 5. out = [y|ya] @ [W_proj|LB*s]^T + b
    {
        dim3 grid(Cc / GBN, Mtot / GBM);
        gemm_lora_tc<<<grid, 256>>>(y, w_proj, b_proj, ya, lb_proj, out, Cc);
    }
}